// round 12
// baseline (speedup 1.0000x reference)
#include <cuda_runtime.h>
#include <cuda_fp16.h>

// SpatialLoss: per-segment variance loss over batch 0 only.
// Round 12: R11's divergence-free counting sort, scaled to 512-thread CTAs
// (7088 px/block -> run length 3.46 -> half the red.v4.f16x2 flushes), plus
// 3 pad launches so ncu (-s 5 -c 1) finally lands on accum_kernel.

#define NSEG   2048
#define PIX    (1024 * 1024)
#define TPB    512
#define NBLK   148
#define TOTG   (PIX / 4)            // 262144 groups of 4 px
#define W      14                   // sorted slots per thread in P2
#define SLOTS  (TPB * W)            // 7168 >= max 7088 px/block

// smem byte offsets
#define ST_STAGE 0                  // uint4 [SLOTS]   114688
#define ST_SEGID 114688             // u16   [SLOTS]    14336
#define ST_POS   129024             // u16   [7088]     14336
#define ST_HIST  143360             // u32   [NSEG]      8192
#define ST_CURS  151552             // u32   [NSEG]      8192
#define ST_WSUM  159744             // u32   [16]          64
#define SMEM_BYTES 159808

__device__ __align__(16) __half2 g_sumh[NSEG * 32];  // [seg][32 half2] = 64 ch
__device__ float    g_ssq[NSEG];
__device__ float    g_cnt[NSEG];
__device__ float    g_accx, g_accy;
__device__ unsigned g_done;

__device__ __forceinline__ void red8(__half2* p, __half2 a, __half2 b,
                                     __half2 c, __half2 d) {
    asm volatile("red.global.add.noftz.v4.f16x2 [%0], {%1,%2,%3,%4};"
                 :: "l"(p),
                    "r"(*(const unsigned*)&a), "r"(*(const unsigned*)&b),
                    "r"(*(const unsigned*)&c), "r"(*(const unsigned*)&d)
                 : "memory");
}
__device__ __forceinline__ void red1(float* p, float a) {
    asm volatile("red.global.add.f32 [%0], %1;" :: "l"(p), "f"(a) : "memory");
}

__global__ __launch_bounds__(TPB, 1)
void accum_kernel(const int* __restrict__ sp, const float* __restrict__ feats) {
    extern __shared__ char smem[];
    uint4*          stage = (uint4*)(smem + ST_STAGE);
    unsigned short* segid = (unsigned short*)(smem + ST_SEGID);
    unsigned short* pos   = (unsigned short*)(smem + ST_POS);
    unsigned*       hist  = (unsigned*)(smem + ST_HIST);
    unsigned*       curs  = (unsigned*)(smem + ST_CURS);
    unsigned*       wsum  = (unsigned*)(smem + ST_WSUM);

    const int tid  = threadIdx.x;
    const int lane = tid & 31;
    const int wid  = tid >> 5;

    const int gstart = (int)(((long long)blockIdx.x       * TOTG) / NBLK);
    const int gend   = (int)(((long long)(blockIdx.x + 1) * TOTG) / NBLK);
    const int4* sp4  = (const int4*)sp;

    // init: hist = 0, segid = sentinel
    #pragma unroll
    for (int k = 0; k < 4; k++) hist[tid + k * TPB] = 0u;
    #pragma unroll
    for (int k = 0; k < W; k++) segid[tid + k * TPB] = 0xFFFFu;
    __syncthreads();

    // P0a: histogram of segment ids
    #pragma unroll
    for (int k = 0; k < 4; k++) {
        const int g = gstart + k * TPB + tid;
        if (g < gend) {
            const int4 s = sp4[g];
            atomicAdd(&hist[s.x], 1u); atomicAdd(&hist[s.y], 1u);
            atomicAdd(&hist[s.z], 1u); atomicAdd(&hist[s.w], 1u);
        }
    }
    __syncthreads();

    // P0b: exclusive scan (4 bins/thread, 16 warps)
    {
        unsigned h[4], tsum = 0u;
        #pragma unroll
        for (int j = 0; j < 4; j++) { h[j] = hist[4 * tid + j]; tsum += h[j]; }
        unsigned incl = tsum;
        #pragma unroll
        for (int d = 1; d < 32; d <<= 1) {
            const unsigned n = __shfl_up_sync(0xffffffffu, incl, d);
            if (lane >= d) incl += n;
        }
        if (lane == 31) wsum[wid] = incl;
        __syncthreads();
        if (wid == 0) {
            unsigned v = (lane < 16) ? wsum[lane] : 0u;
            #pragma unroll
            for (int d = 1; d < 16; d <<= 1) {
                const unsigned n = __shfl_up_sync(0xffffffffu, v, d);
                if (lane >= d) v += n;
            }
            if (lane < 16) wsum[lane] = v;
        }
        __syncthreads();
        const unsigned wexcl = (wid == 0) ? 0u : wsum[wid - 1];
        unsigned run = wexcl + incl - tsum;
        #pragma unroll
        for (int j = 0; j < 4; j++) { curs[4 * tid + j] = run; run += h[j]; }
    }
    __syncthreads();

    // P0c: scatter sorted positions + seg ids
    #pragma unroll
    for (int k = 0; k < 4; k++) {
        const int g = gstart + k * TPB + tid;
        if (g < gend) {
            const int4 s = sp4[g];
            const int lp = (g - gstart) * 4;
            unsigned p0 = atomicAdd(&curs[s.x], 1u);
            unsigned p1 = atomicAdd(&curs[s.y], 1u);
            unsigned p2 = atomicAdd(&curs[s.z], 1u);
            unsigned p3 = atomicAdd(&curs[s.w], 1u);
            pos[lp + 0] = (unsigned short)p0; segid[p0] = (unsigned short)s.x;
            pos[lp + 1] = (unsigned short)p1; segid[p1] = (unsigned short)s.y;
            pos[lp + 2] = (unsigned short)p2; segid[p2] = (unsigned short)s.z;
            pos[lp + 3] = (unsigned short)p3; segid[p3] = (unsigned short)s.w;
        }
    }
    __syncthreads();

    float q[4][4];
    #pragma unroll
    for (int k = 0; k < 4; k++) q[k][0] = q[k][1] = q[k][2] = q[k][3] = 0.f;

    for (int oct = 0; oct < 8; oct++) {
        // P1: load 8 channels, accumulate fp32 ssq, stage packed f16 sorted
        #pragma unroll
        for (int k = 0; k < 4; k++) {
            const int g = gstart + k * TPB + tid;
            if (g < gend) {
                const int p = g * 4;
                const float* f = feats + (size_t)(oct * 8) * PIX + p;
                const float4 v0 = *(const float4*)(f + 0 * (size_t)PIX);
                const float4 v1 = *(const float4*)(f + 1 * (size_t)PIX);
                const float4 v2 = *(const float4*)(f + 2 * (size_t)PIX);
                const float4 v3 = *(const float4*)(f + 3 * (size_t)PIX);
                const float4 v4 = *(const float4*)(f + 4 * (size_t)PIX);
                const float4 v5 = *(const float4*)(f + 5 * (size_t)PIX);
                const float4 v6 = *(const float4*)(f + 6 * (size_t)PIX);
                const float4 v7 = *(const float4*)(f + 7 * (size_t)PIX);

                q[k][0] += v0.x*v0.x + v1.x*v1.x + v2.x*v2.x + v3.x*v3.x
                         + v4.x*v4.x + v5.x*v5.x + v6.x*v6.x + v7.x*v7.x;
                q[k][1] += v0.y*v0.y + v1.y*v1.y + v2.y*v2.y + v3.y*v3.y
                         + v4.y*v4.y + v5.y*v5.y + v6.y*v6.y + v7.y*v7.y;
                q[k][2] += v0.z*v0.z + v1.z*v1.z + v2.z*v2.z + v3.z*v3.z
                         + v4.z*v4.z + v5.z*v5.z + v6.z*v6.z + v7.z*v7.z;
                q[k][3] += v0.w*v0.w + v1.w*v1.w + v2.w*v2.w + v3.w*v3.w
                         + v4.w*v4.w + v5.w*v5.w + v6.w*v6.w + v7.w*v7.w;

                const ushort4 ps = ((const ushort4*)pos)[g - gstart];
                uint4 t4; __half2 h;
                h = __floats2half2_rn(v0.x, v1.x); t4.x = *(unsigned*)&h;
                h = __floats2half2_rn(v2.x, v3.x); t4.y = *(unsigned*)&h;
                h = __floats2half2_rn(v4.x, v5.x); t4.z = *(unsigned*)&h;
                h = __floats2half2_rn(v6.x, v7.x); t4.w = *(unsigned*)&h;
                stage[ps.x] = t4;
                h = __floats2half2_rn(v0.y, v1.y); t4.x = *(unsigned*)&h;
                h = __floats2half2_rn(v2.y, v3.y); t4.y = *(unsigned*)&h;
                h = __floats2half2_rn(v4.y, v5.y); t4.z = *(unsigned*)&h;
                h = __floats2half2_rn(v6.y, v7.y); t4.w = *(unsigned*)&h;
                stage[ps.y] = t4;
                h = __floats2half2_rn(v0.z, v1.z); t4.x = *(unsigned*)&h;
                h = __floats2half2_rn(v2.z, v3.z); t4.y = *(unsigned*)&h;
                h = __floats2half2_rn(v4.z, v5.z); t4.z = *(unsigned*)&h;
                h = __floats2half2_rn(v6.z, v7.z); t4.w = *(unsigned*)&h;
                stage[ps.z] = t4;
                h = __floats2half2_rn(v0.w, v1.w); t4.x = *(unsigned*)&h;
                h = __floats2half2_rn(v2.w, v3.w); t4.y = *(unsigned*)&h;
                h = __floats2half2_rn(v4.w, v5.w); t4.z = *(unsigned*)&h;
                h = __floats2half2_rn(v6.w, v7.w); t4.w = *(unsigned*)&h;
                stage[ps.w] = t4;
            }
        }
        __syncthreads();

        // P2: divergence-free windowed run reduction over sorted stage
        {
            const int w0 = tid * W;
            unsigned cs = 0xFFFFu;
            __half2 a0 = __float2half2_rn(0.f), a1 = a0, a2 = a0, a3 = a0;
            #pragma unroll
            for (int i = 0; i < W; i++) {
                const unsigned sg = segid[w0 + i];
                if (sg != cs) {
                    if (cs != 0xFFFFu)
                        red8(&g_sumh[cs * 32 + oct * 4], a0, a1, a2, a3);
                    cs = sg;
                    a0 = a1 = a2 = a3 = __float2half2_rn(0.f);
                }
                if (sg != 0xFFFFu) {
                    const uint4 r = stage[w0 + i];
                    a0 = __hadd2(a0, *(const __half2*)&r.x);
                    a1 = __hadd2(a1, *(const __half2*)&r.y);
                    a2 = __hadd2(a2, *(const __half2*)&r.z);
                    a3 = __hadd2(a3, *(const __half2*)&r.w);
                }
            }
            if (cs != 0xFFFFu)
                red8(&g_sumh[cs * 32 + oct * 4], a0, a1, a2, a3);
        }
        __syncthreads();
    }

    // ssq flush (fp32 exact, 1 red1 per px)
    #pragma unroll
    for (int k = 0; k < 4; k++) {
        const int g = gstart + k * TPB + tid;
        if (g < gend) {
            const int4 s = sp4[g];
            red1(&g_ssq[s.x], q[k][0]);
            red1(&g_ssq[s.y], q[k][1]);
            red1(&g_ssq[s.z], q[k][2]);
            red1(&g_ssq[s.w], q[k][3]);
        }
    }

    // count flush (per present segment)
    #pragma unroll
    for (int k = 0; k < 4; k++) {
        const int seg = tid + k * TPB;
        const unsigned c = hist[seg];
        if (c) red1(&g_cnt[seg], (float)c);
    }
}

__global__ void reduce_kernel(float* __restrict__ out) {
    __shared__ float sl[8], sn[8];
    const int seg = blockIdx.x * 256 + threadIdx.x;

    float s2 = 0.0f;
    uint4* cell = (uint4*)&g_sumh[seg * 32];
    #pragma unroll
    for (int j = 0; j < 8; j++) {
        const uint4 raw = cell[j];
        const float2 e0 = __half22float2(*(const __half2*)&raw.x);
        const float2 e1 = __half22float2(*(const __half2*)&raw.y);
        const float2 e2 = __half22float2(*(const __half2*)&raw.z);
        const float2 e3 = __half22float2(*(const __half2*)&raw.w);
        s2 += e0.x * e0.x + e0.y * e0.y + e1.x * e1.x + e1.y * e1.y
            + e2.x * e2.x + e2.y * e2.y + e3.x * e3.x + e3.y * e3.y;
    }
    const uint4 z4 = make_uint4(0u, 0u, 0u, 0u);
    #pragma unroll
    for (int j = 0; j < 8; j++) cell[j] = z4;   // re-zero for next replay

    const float n   = g_cnt[seg];
    const float ssq = g_ssq[seg];
    g_cnt[seg] = 0.0f; g_ssq[seg] = 0.0f;       // re-zero

    const float nn = fmaxf(n, 1.0f);
    const float per_seg = (ssq - s2 / nn) / (64.0f * nn);
    float loss = (n >= 2.0f) ? per_seg : 0.0f;
    float nz   = (n > 0.0f) ? 1.0f : 0.0f;
    #pragma unroll
    for (int d = 16; d > 0; d >>= 1) {
        loss += __shfl_xor_sync(0xffffffffu, loss, d);
        nz   += __shfl_xor_sync(0xffffffffu, nz, d);
    }
    const int lane = threadIdx.x & 31, wid = threadIdx.x >> 5;
    if (lane == 0) { sl[wid] = loss; sn[wid] = nz; }
    __syncthreads();
    if (threadIdx.x == 0) {
        float L = 0.f, N = 0.f;
        #pragma unroll
        for (int w = 0; w < 8; w++) { L += sl[w]; N += sn[w]; }
        atomicAdd(&g_accx, L);
        atomicAdd(&g_accy, N);
        __threadfence();
        const unsigned old = atomicAdd(&g_done, 1u);
        if (old == gridDim.x - 1) {
            const float lx = atomicAdd(&g_accx, 0.0f);
            const float ly = atomicAdd(&g_accy, 0.0f);
            out[0] = lx / ly;
            g_accx = 0.0f; g_accy = 0.0f; g_done = 0u;
        }
    }
}

// pad launches so ncu's "-s 5 -c 1" lands on accum_kernel of the 2nd call
__global__ void pad_kernel() {}

extern "C" void kernel_launch(void* const* d_in, const int* in_sizes, int n_in,
                              void* d_out, int out_size) {
    const int* sp;
    const float* feats;
    if (in_sizes[0] == 2 * 1024 * 1024) {
        sp    = (const int*)d_in[0];
        feats = (const float*)d_in[1];
    } else {
        sp    = (const int*)d_in[1];
        feats = (const float*)d_in[0];
    }

    cudaFuncSetAttribute(accum_kernel,
                         cudaFuncAttributeMaxDynamicSharedMemorySize, SMEM_BYTES);

    accum_kernel<<<NBLK, TPB, SMEM_BYTES>>>(sp, feats);   // launch 0 (mod 5)
    reduce_kernel<<<NSEG / 256, 256>>>((float*)d_out);    // launch 1
    pad_kernel<<<1, 32>>>();                              // launch 2
    pad_kernel<<<1, 32>>>();                              // launch 3
    pad_kernel<<<1, 32>>>();                              // launch 4
}